// round 15
// baseline (speedup 1.0000x reference)
#include <cuda_runtime.h>
#include <cuda_bf16.h>
#include <cstdint>

#define DD 2048
#define BB 256
#define TT 64

// scratch (static device arrays — no allocations)
__device__ float          g_u [BB * DD];   // 2 MB (phase0 acc, then final u)
__device__ __nv_bfloat16  g_Eh[BB * DD];   // 1 MB
__device__ __nv_bfloat16  g_Wh[DD * DD];   // 8 MB: bf16(W - I)

// ---------------------------------------------------------------------------
// conv: phase 0 = E + W rows [0,1024);  phase 1 = W rows [1024,2048).
// R10-proven body: 1 thread = 2 float4 -> one uint4 store.
// ---------------------------------------------------------------------------
__global__ __launch_bounds__(256) void conv_kernel(
    const float* __restrict__ E, const float* __restrict__ W, int phase)
{
    const int NWP2 = DD * DD / 16;            // 262144 W pairs per half
    const int j = blockIdx.x * 256 + threadIdx.x;

    int wp = -1;
    if (phase == 1)          wp = j + NWP2;   // rows 1024+
    else if (j < NWP2)       wp = j;          // rows 0..1023
    if (wp >= 0) {
        float4 a = reinterpret_cast<const float4*>(W)[wp * 2];
        float4 b = reinterpret_cast<const float4*>(W)[wp * 2 + 1];
        const int fbase = wp * 8;
        const int r = fbase >> 11;
        const int d = r - (fbase & (DD - 1));
        if (d >= 0 && d < 4)      reinterpret_cast<float*>(&a)[d]     -= 1.0f;
        else if (d >= 4 && d < 8) reinterpret_cast<float*>(&b)[d - 4] -= 1.0f;
        __nv_bfloat162 p0 = __floats2bfloat162_rn(a.x, a.y);
        __nv_bfloat162 p1 = __floats2bfloat162_rn(a.z, a.w);
        __nv_bfloat162 p2 = __floats2bfloat162_rn(b.x, b.y);
        __nv_bfloat162 p3 = __floats2bfloat162_rn(b.z, b.w);
        uint4 o;
        o.x = *reinterpret_cast<uint32_t*>(&p0);
        o.y = *reinterpret_cast<uint32_t*>(&p1);
        o.z = *reinterpret_cast<uint32_t*>(&p2);
        o.w = *reinterpret_cast<uint32_t*>(&p3);
        reinterpret_cast<uint4*>(g_Wh)[wp] = o;
    } else {
        const int k = j - NWP2;               // E pair (phase 0 only)
        float4 a = reinterpret_cast<const float4*>(E)[k * 2];
        float4 b = reinterpret_cast<const float4*>(E)[k * 2 + 1];
        __nv_bfloat162 p0 = __floats2bfloat162_rn(a.x, a.y);
        __nv_bfloat162 p1 = __floats2bfloat162_rn(a.z, a.w);
        __nv_bfloat162 p2 = __floats2bfloat162_rn(b.x, b.y);
        __nv_bfloat162 p3 = __floats2bfloat162_rn(b.z, b.w);
        uint4 o;
        o.x = *reinterpret_cast<uint32_t*>(&p0);
        o.y = *reinterpret_cast<uint32_t*>(&p1);
        o.z = *reinterpret_cast<uint32_t*>(&p2);
        o.w = *reinterpret_cast<uint32_t*>(&p3);
        reinterpret_cast<uint4*>(g_Eh)[k] = o;
    }
}

// ---------------------------------------------------------------------------
// helpers (proven)
// ---------------------------------------------------------------------------
__device__ __forceinline__ void mma16816(float* d, const uint32_t* a,
                                         uint32_t b0, uint32_t b1)
{
    asm volatile(
        "mma.sync.aligned.m16n8k16.row.col.f32.bf16.bf16.f32 "
        "{%0,%1,%2,%3}, {%4,%5,%6,%7}, {%8,%9}, {%0,%1,%2,%3};\n"
        : "+f"(d[0]), "+f"(d[1]), "+f"(d[2]), "+f"(d[3])
        : "r"(a[0]), "r"(a[1]), "r"(a[2]), "r"(a[3]), "r"(b0), "r"(b1));
}
__device__ __forceinline__ void ldsm_x4(uint32_t* r, uint32_t addr)
{
    asm volatile("ldmatrix.sync.aligned.m8n8.x4.shared.b16 {%0,%1,%2,%3}, [%4];\n"
                 : "=r"(r[0]), "=r"(r[1]), "=r"(r[2]), "=r"(r[3]) : "r"(addr));
}
__device__ __forceinline__ void ldsm_x4_t(uint32_t* r, uint32_t addr)
{
    asm volatile("ldmatrix.sync.aligned.m8n8.x4.trans.shared.b16 {%0,%1,%2,%3}, [%4];\n"
                 : "=r"(r[0]), "=r"(r[1]), "=r"(r[2]), "=r"(r[3]) : "r"(addr));
}
__device__ __forceinline__ void cp16(uint32_t saddr, const void* gaddr)
{
    asm volatile("cp.async.cg.shared.global [%0], [%1], 16;\n"
                 :: "r"(saddr), "l"(gaddr) : "memory");
}

// ---------------------------------------------------------------------------
// Kernel A: K-split tensor-core GEMM (R10 proven 6-stage ring, 16 iters).
//   phase 0 (kBase=0,    fin=0): g_u  = acc
//   phase 1 (kBase=1024, fin=1): g_u += acc + E + hb
// ---------------------------------------------------------------------------
__global__ __launch_bounds__(256) void gemm_u_kernel(
    const float* __restrict__ E, const float* __restrict__ hb,
    int kBase, int fin)
{
    extern __shared__ __align__(1024) char smem[];
    const uint32_t base = (uint32_t)__cvta_generic_to_shared(smem);

    const int tid  = threadIdx.x;
    const int lane = tid & 31;
    const int wid  = tid >> 5;
    const int wm   = (wid >> 2) << 5;
    const int wn   = (wid & 3) << 4;
    const int bm   = blockIdx.y << 6;
    const int bn   = blockIdx.x << 6;

    float acc[2][2][4];
    #pragma unroll
    for (int i = 0; i < 2; i++)
        #pragma unroll
        for (int j = 0; j < 2; j++)
            #pragma unroll
            for (int k = 0; k < 4; k++) acc[i][j][k] = 0.f;

    const int r0 = tid >> 3;
    const int c0 = tid & 7;
    const uint32_t swzOff  = (uint32_t)((r0 << 7) + ((c0 ^ (r0 & 7)) << 4));
    const uint32_t swzOff2 = swzOff + (32 << 7);

    const __nv_bfloat16* gA  = g_Eh + (size_t)(bm + r0) * DD + kBase + c0 * 8;
    const __nv_bfloat16* gA2 = gA + (size_t)32 * DD;
    const __nv_bfloat16* gB  = g_Wh + (size_t)(kBase + r0) * DD + bn + c0 * 8;
    const __nv_bfloat16* gB2 = gB + (size_t)32 * DD;

    const int l15 = lane & 15;
    const int l7  = lane & 7;
    const int kcB = lane >> 4;
    uint32_t aRow[2];
    #pragma unroll
    for (int im = 0; im < 2; im++) aRow[im] = (uint32_t)((wm + im * 16 + l15) << 7);
    const int nChunkBase = wn >> 3;

    #define LOAD_TILES(stg, k0)                                            \
        {                                                                  \
            const uint32_t sa = base + (uint32_t)((stg) * 8192);           \
            const uint32_t sb = base + 49152u + (uint32_t)((stg) * 8192);  \
            cp16(sa + swzOff,  gA  + (k0));                                \
            cp16(sa + swzOff2, gA2 + (k0));                                \
            cp16(sb + swzOff,  gB  + (size_t)(k0) * DD);                   \
            cp16(sb + swzOff2, gB2 + (size_t)(k0) * DD);                   \
            asm volatile("cp.async.commit_group;\n" ::: "memory");         \
        }

    #pragma unroll
    for (int p = 0; p < 5; p++) LOAD_TILES(p, p * 64);

    const int NIT = 1024 / 64;   // 16
    for (int it = 0; it < NIT; it++) {
        if (it + 4 < NIT)
            asm volatile("cp.async.wait_group 4;\n" ::: "memory");
        else
            asm volatile("cp.async.wait_group 0;\n" ::: "memory");
        __syncthreads();

        if (it + 5 < NIT) LOAD_TILES((it + 5) % 6, (it + 5) * 64);

        const int s = it % 6;
        const uint32_t sa = base + (uint32_t)(s * 8192);
        const uint32_t sb = base + 49152u + (uint32_t)(s * 8192);
        #pragma unroll
        for (int kk = 0; kk < 4; kk++) {
            uint32_t a[2][4], b[4];
            const int kchunk = kk * 2 + kcB;
            #pragma unroll
            for (int im = 0; im < 2; im++)
                ldsm_x4(a[im], sa + aRow[im] + (uint32_t)((kchunk ^ l7) << 4));
            {
                const int krow = kk * 16 + l15;
                const int nchunk = nChunkBase + kcB;
                ldsm_x4_t(b, sb + (uint32_t)(krow << 7)
                               + (uint32_t)((nchunk ^ (krow & 7)) << 4));
            }
            #pragma unroll
            for (int im = 0; im < 2; im++) {
                mma16816(acc[im][0], a[im], b[0], b[1]);
                mma16816(acc[im][1], a[im], b[2], b[3]);
            }
        }
    }
    #undef LOAD_TILES

    // epilogue
    #pragma unroll
    for (int im = 0; im < 2; im++) {
        const int row0e = bm + wm + im * 16 + (lane >> 2);
        #pragma unroll
        for (int in = 0; in < 2; in++) {
            const int col = bn + wn + in * 8 + ((lane & 3) << 1);
            float* u00 = &g_u[(size_t)row0e * DD + col];
            float* u10 = &g_u[(size_t)(row0e + 8) * DD + col];
            if (fin) {
                const float h0 = hb[col], h1 = hb[col + 1];
                u00[0] += acc[im][in][0] + E[(size_t)row0e * DD + col] + h0;
                u00[1] += acc[im][in][1] + E[(size_t)row0e * DD + col + 1] + h1;
                u10[0] += acc[im][in][2] + E[(size_t)(row0e + 8) * DD + col] + h0;
                u10[1] += acc[im][in][3] + E[(size_t)(row0e + 8) * DD + col + 1] + h1;
            } else {
                u00[0] = acc[im][in][0];
                u00[1] = acc[im][in][1];
                u10[0] = acc[im][in][2];
                u10[1] = acc[im][in][3];
            }
        }
    }
}

// ---------------------------------------------------------------------------
// Kernel B: scoring (R8/R10 passing version, verbatim). Single wave:
// grid (256, 8) x 128 thr, 16 CTAs/SM.
// ---------------------------------------------------------------------------
__global__ __launch_bounds__(128, 16) void score_kernel(
    const float* __restrict__ E,
    const float* __restrict__ theo,
    const float* __restrict__ cand,
    const float* __restrict__ vb,
    float* __restrict__ out)
{
    const int b    = blockIdx.x;
    const int tc   = blockIdx.y;       // 0..7
    const int tid  = threadIdx.x;
    const int lane = tid & 31;
    const int wid  = tid >> 5;         // 0..3

    __shared__ float u_s[DD];
    __shared__ float red[8];
    __shared__ float s_vb, s_pos;

    float pv = 0.f, pp = 0.f;
    #pragma unroll
    for (int h = 0; h < 4; h++) {
        const int i = h * 512 + tid * 4;
        float4 u4 = *reinterpret_cast<const float4*>(&g_u[(size_t)b * DD + i]);
        *reinterpret_cast<float4*>(&u_s[i]) = u4;
        float4 e4 = *reinterpret_cast<const float4*>(&E[(size_t)b * DD + i]);
        float4 v4 = *reinterpret_cast<const float4*>(&vb[i]);
        pv += e4.x * v4.x + e4.y * v4.y + e4.z * v4.z + e4.w * v4.w;
        if (tc == 0) {
            float4 c4 = *reinterpret_cast<const float4*>(&cand[(size_t)b * DD + i]);
            pp += u4.x * c4.x + u4.y * c4.y + u4.z * c4.z + u4.w * c4.w;
        }
    }
    #pragma unroll
    for (int o = 16; o > 0; o >>= 1) {
        pv += __shfl_xor_sync(0xFFFFFFFFu, pv, o);
        pp += __shfl_xor_sync(0xFFFFFFFFu, pp, o);
    }
    if (lane == 0) { red[wid] = pv; red[4 + wid] = pp; }
    __syncthreads();
    if (tid == 0) {
        float v = red[0] + red[1] + red[2] + red[3];
        float p = red[4] + red[5] + red[6] + red[7];
        s_vb  = v;
        s_pos = p + v;
    }
    __syncthreads();
    const float vbb = s_vb;

    const int t0 = tc * 8 + wid * 2;
    const float4* ra  = reinterpret_cast<const float4*>(&theo[((size_t)b * TT + t0) * DD]);
    const float4* rb  = ra + DD / 4;
    const float4* u4p = reinterpret_cast<const float4*>(u_s);

    float s0 = 0.f, s1 = 0.f;
    #pragma unroll 4
    for (int i = lane; i < DD / 4; i += 32) {
        float4 x = __ldcs(&ra[i]);
        float4 y = __ldcs(&rb[i]);
        float4 u = u4p[i];
        s0 += x.x * u.x + x.y * u.y + x.z * u.z + x.w * u.w;
        s1 += y.x * u.x + y.y * u.y + y.z * u.z + y.w * u.w;
    }
    #pragma unroll
    for (int o = 16; o > 0; o >>= 1) {
        s0 += __shfl_xor_sync(0xFFFFFFFFu, s0, o);
        s1 += __shfl_xor_sync(0xFFFFFFFFu, s1, o);
    }
    if (lane == 0) {
        out[b * (TT + 1) + 1 + t0]     = s0 + vbb;
        out[b * (TT + 1) + 1 + t0 + 1] = s1 + vbb;
    }
    if (tc == 0 && tid == 0) out[b * (TT + 1)] = s_pos;
}

// ---------------------------------------------------------------------------
// launch: conv0 -> fork { conv1 on s1  ∥  gemm_p0 on stream 0 } -> join ->
//         gemm_p1 -> score.  No device-side sync; plain co-scheduling.
// ---------------------------------------------------------------------------
extern "C" void kernel_launch(void* const* d_in, const int* in_sizes, int n_in,
                              void* d_out, int out_size)
{
    const float* E    = (const float*)d_in[0];
    const float* theo = (const float*)d_in[1];
    const float* cand = (const float*)d_in[2];
    const float* W    = (const float*)d_in[3];
    const float* vb   = (const float*)d_in[4];
    const float* hb   = (const float*)d_in[5];
    float*       out  = (float*)d_out;

    static cudaStream_t s1 = nullptr;
    static cudaEvent_t evA, evC;
    if (!s1) {
        cudaStreamCreateWithFlags(&s1, cudaStreamNonBlocking);
        cudaEventCreateWithFlags(&evA, cudaEventDisableTiming);
        cudaEventCreateWithFlags(&evC, cudaEventDisableTiming);
        cudaFuncSetAttribute(gemm_u_kernel,
                             cudaFuncAttributeMaxDynamicSharedMemorySize, 12 * 8192);
    }
    const int SMEM = 12 * 8192;   // 96 KB

    // phase 0 convert: E (65536 pairs) + W rows 0-1023 (262144 pairs)
    conv_kernel<<<(262144 + 65536) / 256, 256>>>(E, W, 0);
    cudaEventRecord(evA, 0);
    cudaStreamWaitEvent(s1, evA, 0);

    // fork: conv phase 1 on s1, concurrent with gemm phase 0 on stream 0
    conv_kernel<<<262144 / 256, 256, 0, s1>>>(E, W, 1);
    cudaEventRecord(evC, s1);

    gemm_u_kernel<<<dim3(DD / 64, BB / 64), 256, SMEM>>>(E, hb, 0, 0);

    // join, then finish GEMM and score
    cudaStreamWaitEvent(0, evC, 0);
    gemm_u_kernel<<<dim3(DD / 64, BB / 64), 256, SMEM>>>(E, hb, 1024, 1);
    score_kernel<<<dim3(BB, 8), 128>>>(E, theo, cand, vb, out);
}

// round 16
// speedup vs baseline: 1.0863x; 1.0863x over previous
#include <cuda_runtime.h>
#include <cuda_bf16.h>
#include <cstdint>

#define DD 2048
#define BB 256
#define TT 64

// scratch (static device arrays — no allocations)
__device__ float          g_u [BB * DD];   // 2 MB
__device__ __nv_bfloat16  g_Eh[BB * DD];   // 1 MB
__device__ __nv_bfloat16  g_Wh[DD * DD];   // 8 MB: bf16(W - I)

// ---------------------------------------------------------------------------
// Kernel 0: convert, CTA-split (blocks 0..1023 = W, 1024..1151 = E).
// Each thread: 4 contiguous float4 loads (64 B, MLP_p1=4), 2 uint4 stores.
// ---------------------------------------------------------------------------
__device__ __forceinline__ uint4 pack8(const float4& a, const float4& b)
{
    __nv_bfloat162 p0 = __floats2bfloat162_rn(a.x, a.y);
    __nv_bfloat162 p1 = __floats2bfloat162_rn(a.z, a.w);
    __nv_bfloat162 p2 = __floats2bfloat162_rn(b.x, b.y);
    __nv_bfloat162 p3 = __floats2bfloat162_rn(b.z, b.w);
    uint4 o;
    o.x = *reinterpret_cast<uint32_t*>(&p0);
    o.y = *reinterpret_cast<uint32_t*>(&p1);
    o.z = *reinterpret_cast<uint32_t*>(&p2);
    o.w = *reinterpret_cast<uint32_t*>(&p3);
    return o;
}

__global__ __launch_bounds__(256) void convert_kernel(
    const float* __restrict__ E, const float* __restrict__ W)
{
    if (blockIdx.x < 1024) {
        // W: thread j handles 16 consecutive floats (one row segment)
        const int j = blockIdx.x * 256 + threadIdx.x;        // 0..262143
        const float4* src = reinterpret_cast<const float4*>(W) + (size_t)j * 4;
        float4 v0 = src[0], v1 = src[1], v2 = src[2], v3 = src[3];
        const int fbase = j * 16;
        const int r = fbase >> 11;
        const int d = r - (fbase & (DD - 1));                // diag offset in [0,16)?
        if (d >= 0 && d < 4)        reinterpret_cast<float*>(&v0)[d]      -= 1.0f;
        else if (d >= 4  && d < 8)  reinterpret_cast<float*>(&v1)[d - 4]  -= 1.0f;
        else if (d >= 8  && d < 12) reinterpret_cast<float*>(&v2)[d - 8]  -= 1.0f;
        else if (d >= 12 && d < 16) reinterpret_cast<float*>(&v3)[d - 12] -= 1.0f;
        uint4* dst = reinterpret_cast<uint4*>(g_Wh) + (size_t)j * 2;
        dst[0] = pack8(v0, v1);
        dst[1] = pack8(v2, v3);
    } else {
        // E: 128 CTAs, thread k handles 16 consecutive floats
        const int k = (blockIdx.x - 1024) * 256 + threadIdx.x;   // 0..32767
        const float4* src = reinterpret_cast<const float4*>(E) + (size_t)k * 4;
        float4 v0 = src[0], v1 = src[1], v2 = src[2], v3 = src[3];
        uint4* dst = reinterpret_cast<uint4*>(g_Eh) + (size_t)k * 2;
        dst[0] = pack8(v0, v1);
        dst[1] = pack8(v2, v3);
    }
}

// ---------------------------------------------------------------------------
// helpers (proven)
// ---------------------------------------------------------------------------
__device__ __forceinline__ void mma16816(float* d, const uint32_t* a,
                                         uint32_t b0, uint32_t b1)
{
    asm volatile(
        "mma.sync.aligned.m16n8k16.row.col.f32.bf16.bf16.f32 "
        "{%0,%1,%2,%3}, {%4,%5,%6,%7}, {%8,%9}, {%0,%1,%2,%3};\n"
        : "+f"(d[0]), "+f"(d[1]), "+f"(d[2]), "+f"(d[3])
        : "r"(a[0]), "r"(a[1]), "r"(a[2]), "r"(a[3]), "r"(b0), "r"(b1));
}
__device__ __forceinline__ void ldsm_x4(uint32_t* r, uint32_t addr)
{
    asm volatile("ldmatrix.sync.aligned.m8n8.x4.shared.b16 {%0,%1,%2,%3}, [%4];\n"
                 : "=r"(r[0]), "=r"(r[1]), "=r"(r[2]), "=r"(r[3]) : "r"(addr));
}
__device__ __forceinline__ void ldsm_x4_t(uint32_t* r, uint32_t addr)
{
    asm volatile("ldmatrix.sync.aligned.m8n8.x4.trans.shared.b16 {%0,%1,%2,%3}, [%4];\n"
                 : "=r"(r[0]), "=r"(r[1]), "=r"(r[2]), "=r"(r[3]) : "r"(addr));
}
__device__ __forceinline__ void cp16(uint32_t saddr, const void* gaddr)
{
    asm volatile("cp.async.cg.shared.global [%0], [%1], 16;\n"
                 :: "r"(saddr), "l"(gaddr) : "memory");
}

// ---------------------------------------------------------------------------
// Kernel A: tensor-core GEMM  U = Eh @ Wh + E + hb  (R10 proven 6-stage ring)
// ---------------------------------------------------------------------------
__global__ __launch_bounds__(256) void gemm_u_kernel(
    const float* __restrict__ E, const float* __restrict__ hb)
{
    extern __shared__ __align__(1024) char smem[];
    const uint32_t base = (uint32_t)__cvta_generic_to_shared(smem);

    const int tid  = threadIdx.x;
    const int lane = tid & 31;
    const int wid  = tid >> 5;
    const int wm   = (wid >> 2) << 5;
    const int wn   = (wid & 3) << 4;
    const int bm   = blockIdx.y << 6;
    const int bn   = blockIdx.x << 6;

    float acc[2][2][4];
    #pragma unroll
    for (int i = 0; i < 2; i++)
        #pragma unroll
        for (int j = 0; j < 2; j++)
            #pragma unroll
            for (int k = 0; k < 4; k++) acc[i][j][k] = 0.f;

    const int r0 = tid >> 3;
    const int c0 = tid & 7;
    const uint32_t swzOff  = (uint32_t)((r0 << 7) + ((c0 ^ (r0 & 7)) << 4));
    const uint32_t swzOff2 = swzOff + (32 << 7);

    const __nv_bfloat16* gA  = g_Eh + (size_t)(bm + r0) * DD + c0 * 8;
    const __nv_bfloat16* gA2 = gA + (size_t)32 * DD;
    const __nv_bfloat16* gB  = g_Wh + (size_t)r0 * DD + bn + c0 * 8;
    const __nv_bfloat16* gB2 = gB + (size_t)32 * DD;

    const int l15 = lane & 15;
    const int l7  = lane & 7;
    const int kcB = lane >> 4;
    uint32_t aRow[2];
    #pragma unroll
    for (int im = 0; im < 2; im++) aRow[im] = (uint32_t)((wm + im * 16 + l15) << 7);
    const int nChunkBase = wn >> 3;

    #define LOAD_TILES(stg, k0)                                            \
        {                                                                  \
            const uint32_t sa = base + (uint32_t)((stg) * 8192);           \
            const uint32_t sb = base + 49152u + (uint32_t)((stg) * 8192);  \
            cp16(sa + swzOff,  gA  + (k0));                                \
            cp16(sa + swzOff2, gA2 + (k0));                                \
            cp16(sb + swzOff,  gB  + (size_t)(k0) * DD);                   \
            cp16(sb + swzOff2, gB2 + (size_t)(k0) * DD);                   \
            asm volatile("cp.async.commit_group;\n" ::: "memory");         \
        }

    #pragma unroll
    for (int p = 0; p < 5; p++) LOAD_TILES(p, p * 64);

    const int NIT = DD / 64;   // 32
    for (int it = 0; it < NIT; it++) {
        if (it + 4 < NIT)
            asm volatile("cp.async.wait_group 4;\n" ::: "memory");
        else
            asm volatile("cp.async.wait_group 0;\n" ::: "memory");
        __syncthreads();

        if (it + 5 < NIT) LOAD_TILES((it + 5) % 6, (it + 5) * 64);

        const int s = it % 6;
        const uint32_t sa = base + (uint32_t)(s * 8192);
        const uint32_t sb = base + 49152u + (uint32_t)(s * 8192);
        #pragma unroll
        for (int kk = 0; kk < 4; kk++) {
            uint32_t a[2][4], b[4];
            const int kchunk = kk * 2 + kcB;
            #pragma unroll
            for (int im = 0; im < 2; im++)
                ldsm_x4(a[im], sa + aRow[im] + (uint32_t)((kchunk ^ l7) << 4));
            {
                const int krow = kk * 16 + l15;
                const int nchunk = nChunkBase + kcB;
                ldsm_x4_t(b, sb + (uint32_t)(krow << 7)
                               + (uint32_t)((nchunk ^ (krow & 7)) << 4));
            }
            #pragma unroll
            for (int im = 0; im < 2; im++) {
                mma16816(acc[im][0], a[im], b[0], b[1]);
                mma16816(acc[im][1], a[im], b[2], b[3]);
            }
        }
    }
    #undef LOAD_TILES

    // epilogue: u = acc + E (exact identity) + hb
    #pragma unroll
    for (int im = 0; im < 2; im++) {
        const int row0e = bm + wm + im * 16 + (lane >> 2);
        #pragma unroll
        for (int in = 0; in < 2; in++) {
            const int col = bn + wn + in * 8 + ((lane & 3) << 1);
            const float h0 = hb[col], h1 = hb[col + 1];
            g_u[(size_t)row0e * DD + col]
                = acc[im][in][0] + E[(size_t)row0e * DD + col] + h0;
            g_u[(size_t)row0e * DD + col + 1]
                = acc[im][in][1] + E[(size_t)row0e * DD + col + 1] + h1;
            g_u[(size_t)(row0e + 8) * DD + col]
                = acc[im][in][2] + E[(size_t)(row0e + 8) * DD + col] + h0;
            g_u[(size_t)(row0e + 8) * DD + col + 1]
                = acc[im][in][3] + E[(size_t)(row0e + 8) * DD + col + 1] + h1;
        }
    }
}

// ---------------------------------------------------------------------------
// Kernel B: scoring (R8/R10 passing version, verbatim). Single wave:
// grid (256, 8) x 128 thr, 16 CTAs/SM.
// ---------------------------------------------------------------------------
__global__ __launch_bounds__(128, 16) void score_kernel(
    const float* __restrict__ E,
    const float* __restrict__ theo,
    const float* __restrict__ cand,
    const float* __restrict__ vb,
    float* __restrict__ out)
{
    const int b    = blockIdx.x;
    const int tc   = blockIdx.y;       // 0..7
    const int tid  = threadIdx.x;
    const int lane = tid & 31;
    const int wid  = tid >> 5;         // 0..3

    __shared__ float u_s[DD];
    __shared__ float red[8];
    __shared__ float s_vb, s_pos;

    float pv = 0.f, pp = 0.f;
    #pragma unroll
    for (int h = 0; h < 4; h++) {
        const int i = h * 512 + tid * 4;
        float4 u4 = *reinterpret_cast<const float4*>(&g_u[(size_t)b * DD + i]);
        *reinterpret_cast<float4*>(&u_s[i]) = u4;
        float4 e4 = *reinterpret_cast<const float4*>(&E[(size_t)b * DD + i]);
        float4 v4 = *reinterpret_cast<const float4*>(&vb[i]);
        pv += e4.x * v4.x + e4.y * v4.y + e4.z * v4.z + e4.w * v4.w;
        if (tc == 0) {
            float4 c4 = *reinterpret_cast<const float4*>(&cand[(size_t)b * DD + i]);
            pp += u4.x * c4.x + u4.y * c4.y + u4.z * c4.z + u4.w * c4.w;
        }
    }
    #pragma unroll
    for (int o = 16; o > 0; o >>= 1) {
        pv += __shfl_xor_sync(0xFFFFFFFFu, pv, o);
        pp += __shfl_xor_sync(0xFFFFFFFFu, pp, o);
    }
    if (lane == 0) { red[wid] = pv; red[4 + wid] = pp; }
    __syncthreads();
    if (tid == 0) {
        float v = red[0] + red[1] + red[2] + red[3];
        float p = red[4] + red[5] + red[6] + red[7];
        s_vb  = v;
        s_pos = p + v;
    }
    __syncthreads();
    const float vbb = s_vb;

    const int t0 = tc * 8 + wid * 2;
    const float4* ra  = reinterpret_cast<const float4*>(&theo[((size_t)b * TT + t0) * DD]);
    const float4* rb  = ra + DD / 4;
    const float4* u4p = reinterpret_cast<const float4*>(u_s);

    float s0 = 0.f, s1 = 0.f;
    #pragma unroll 4
    for (int i = lane; i < DD / 4; i += 32) {
        float4 x = __ldcs(&ra[i]);
        float4 y = __ldcs(&rb[i]);
        float4 u = u4p[i];
        s0 += x.x * u.x + x.y * u.y + x.z * u.z + x.w * u.w;
        s1 += y.x * u.x + y.y * u.y + y.z * u.z + y.w * u.w;
    }
    #pragma unroll
    for (int o = 16; o > 0; o >>= 1) {
        s0 += __shfl_xor_sync(0xFFFFFFFFu, s0, o);
        s1 += __shfl_xor_sync(0xFFFFFFFFu, s1, o);
    }
    if (lane == 0) {
        out[b * (TT + 1) + 1 + t0]     = s0 + vbb;
        out[b * (TT + 1) + 1 + t0 + 1] = s1 + vbb;
    }
    if (tc == 0 && tid == 0) out[b * (TT + 1)] = s_pos;
}

// ---------------------------------------------------------------------------
// launch: 0=experimental [B,D], 1=theoretical [B,T,D], 2=candidate [B,D],
//         3=W [D,D], 4=vb [D], 5=hb [D] ; out fp32 [B, 1+T]
// ---------------------------------------------------------------------------
extern "C" void kernel_launch(void* const* d_in, const int* in_sizes, int n_in,
                              void* d_out, int out_size)
{
    const float* E    = (const float*)d_in[0];
    const float* theo = (const float*)d_in[1];
    const float* cand = (const float*)d_in[2];
    const float* W    = (const float*)d_in[3];
    const float* vb   = (const float*)d_in[4];
    const float* hb   = (const float*)d_in[5];
    float*       out  = (float*)d_out;

    const int SMEM = 12 * 8192;   // 96 KB dynamic
    cudaFuncSetAttribute(gemm_u_kernel,
                         cudaFuncAttributeMaxDynamicSharedMemorySize, SMEM);

    convert_kernel<<<1152, 256>>>(E, W);
    gemm_u_kernel<<<dim3(DD / 64, BB / 64), 256, SMEM>>>(E, hb);
    score_kernel<<<dim3(BB, 8), 128>>>(E, theo, cand, vb, out);
}